// round 8
// baseline (speedup 1.0000x reference)
#include <cuda_runtime.h>
#include <cuda_bf16.h>
#include <cstdint>
#include <math.h>

#define NB 8
#define NN 2048
#define DD 128
#define ROWS_TOT (NB * NN)

__device__ float g_buf[ROWS_TOT * DD];
__device__ __nv_bfloat16 g_hhi[ROWS_TOT * DD];
__device__ __nv_bfloat16 g_hlo[ROWS_TOT * DD];
__device__ float g_rn[ROWS_TOT];

// ---------------------------------------------------------------------------
__device__ __forceinline__ uint32_t smem_u32(const void* p) {
    uint32_t a;
    asm("{ .reg .u64 t; cvta.to.shared.u64 t, %1; cvt.u32.u64 %0, t; }" : "=r"(a) : "l"(p));
    return a;
}
__device__ __forceinline__ void mma_bf16(float* d, const uint32_t* a, const uint32_t* b) {
    asm volatile(
        "mma.sync.aligned.m16n8k16.row.col.f32.bf16.bf16.f32 "
        "{%0,%1,%2,%3}, {%4,%5,%6,%7}, {%8,%9}, {%0,%1,%2,%3};"
        : "+f"(d[0]), "+f"(d[1]), "+f"(d[2]), "+f"(d[3])
        : "r"(a[0]), "r"(a[1]), "r"(a[2]), "r"(a[3]), "r"(b[0]), "r"(b[1]));
}
__device__ __forceinline__ void ldsm4(uint32_t* r, uint32_t addr) {
    asm volatile("ldmatrix.sync.aligned.m8n8.x4.shared.b16 {%0,%1,%2,%3}, [%4];"
                 : "=r"(r[0]), "=r"(r[1]), "=r"(r[2]), "=r"(r[3]) : "r"(addr));
}
__device__ __forceinline__ void ldsm4t(uint32_t* r, uint32_t addr) {
    asm volatile("ldmatrix.sync.aligned.m8n8.x4.trans.shared.b16 {%0,%1,%2,%3}, [%4];"
                 : "=r"(r[0]), "=r"(r[1]), "=r"(r[2]), "=r"(r[3]) : "r"(addr));
}
__device__ __forceinline__ uint32_t packbf(float a, float b) {
    const uint16_t la = __bfloat16_as_ushort(__float2bfloat16(a));
    const uint16_t lb = __bfloat16_as_ushort(__float2bfloat16(b));
    return ((uint32_t)lb << 16) | la;
}
__device__ __forceinline__ void split2(float v0, float v1, uint32_t& hi, uint32_t& lo) {
    const __nv_bfloat16 h0 = __float2bfloat16(v0);
    const __nv_bfloat16 h1 = __float2bfloat16(v1);
    const float r0 = v0 - __bfloat162float(h0);
    const float r1 = v1 - __bfloat162float(h1);
    hi = ((uint32_t)__bfloat16_as_ushort(h1) << 16) | __bfloat16_as_ushort(h0);
    lo = packbf(r0, r1);
}
#define CP_ASYNC16(dst, src) \
    asm volatile("cp.async.cg.shared.global [%0], [%1], 16;" :: "r"(dst), "l"(src))
#define CP_COMMIT() asm volatile("cp.async.commit_group;" ::: "memory")
#define CP_WAIT(n)  asm volatile("cp.async.wait_group %0;" :: "n"(n) : "memory")

// ---------------------------------------------------------------------------
// Linear + bias + split + reciprocal norm (unchanged, proven)
// ---------------------------------------------------------------------------
#define SMEM_LIN ((64 * 132 + 128 * 132) * 4)

__global__ __launch_bounds__(256, 2) void linear_norm_kernel(
    const float* __restrict__ in, const float* __restrict__ W, const float* __restrict__ bias,
    __nv_bfloat16* __restrict__ hhi, __nv_bfloat16* __restrict__ hlo, float* __restrict__ rn)
{
    extern __shared__ float sm[];
    float* sx = sm;
    float* sw = sm + 64 * 132;

    const int t = threadIdx.x;
    const int rowbase = blockIdx.x * 64;
    const int f4 = (t & 31) * 4;
    const int r0 = t >> 5;

    #pragma unroll
    for (int r = r0; r < 64; r += 8)
        *(float4*)&sx[r * 132 + f4] = *(const float4*)&in[(size_t)(rowbase + r) * DD + f4];
    #pragma unroll
    for (int r = r0; r < 128; r += 8)
        *(float4*)&sw[r * 132 + f4] = *(const float4*)&W[(size_t)r * DD + f4];
    __syncthreads();

    const int tx = t & 15;
    const int ty = t >> 4;

    float acc[4][8];
    #pragma unroll
    for (int i = 0; i < 4; i++)
        #pragma unroll
        for (int j = 0; j < 8; j++) acc[i][j] = 0.0f;

    #pragma unroll 4
    for (int k = 0; k < DD; k++) {
        float a[4], w[8];
        #pragma unroll
        for (int i = 0; i < 4; i++) a[i] = sx[(ty * 4 + i) * 132 + k];
        #pragma unroll
        for (int j = 0; j < 8; j++) w[j] = sw[k * 132 + tx + 16 * j];
        #pragma unroll
        for (int i = 0; i < 4; i++)
            #pragma unroll
            for (int j = 0; j < 8; j++)
                acc[i][j] = fmaf(a[i], w[j], acc[i][j]);
    }

    float bv[8];
    #pragma unroll
    for (int j = 0; j < 8; j++) bv[j] = bias[tx + 16 * j];

    #pragma unroll
    for (int i = 0; i < 4; i++) {
        float ss = 0.0f;
        #pragma unroll
        for (int j = 0; j < 8; j++) {
            acc[i][j] += bv[j];
            ss = fmaf(acc[i][j], acc[i][j], ss);
        }
        #pragma unroll
        for (int off = 8; off > 0; off >>= 1)
            ss += __shfl_xor_sync(0xffffffffu, ss, off, 16);
        if (tx == 0)
            rn[rowbase + ty * 4 + i] = 1.0f / fmaxf(sqrtf(ss), 1e-12f);
    }

    #pragma unroll
    for (int i = 0; i < 4; i++)
        #pragma unroll
        for (int j = 0; j < 8; j++) {
            const float v = acc[i][j];
            const __nv_bfloat16 h = __float2bfloat16(v);
            const __nv_bfloat16 l = __float2bfloat16(v - __bfloat162float(h));
            const size_t idx = (size_t)(rowbase + ty * 4 + i) * DD + tx + 16 * j;
            hhi[idx] = h;
            hlo[idx] = l;
        }
}

// ---------------------------------------------------------------------------
// Fused flash aggregation. 256 threads = 8 warps, 128 p-rows/CTA, grid 128.
// R5 loop skeleton (two syncs, CP_WAIT(1) prefetch) + interleaved HMMA
// accumulators to break dependency chains.
// ---------------------------------------------------------------------------
#define QT 64
#define HQS 136                         // bf16 elems per smem row (272 B)
#define TILE_B (QT * HQS * 2)           // 17408 B per (hi|lo) Hq tile
#define EWS 72                          // ew smem row stride (floats)
#define EW_B (128 * EWS * 4)
#define RQ_B 256
#define STAGE_EW_B (EW_B + RQ_B)
#define OFF_EW (4 * TILE_B)
#define SMEM_FUSED (OFF_EW + 2 * STAGE_EW_B)

__global__ __launch_bounds__(256, 1) void fused_mma_kernel(
    const __nv_bfloat16* __restrict__ hhi, const __nv_bfloat16* __restrict__ hlo,
    const float* __restrict__ rn, const float* __restrict__ ew,
    float* __restrict__ out, int do_relu)
{
    extern __shared__ char smem[];
    const uint32_t sbase = smem_u32(smem);

    const int t = threadIdx.x;
    const int w = t >> 5;
    const int lane = t & 31;
    const int quad = lane & 3;
    const int gr = lane >> 2;
    const int b = blockIdx.y;
    const int pbase = blockIdx.x * 128;

    const __nv_bfloat16* hhB = hhi + (size_t)b * NN * DD;
    const __nv_bfloat16* hlB = hlo + (size_t)b * NN * DD;
    const float* rnB = rn + (size_t)b * NN;
    const float* ewB = ew + (size_t)b * NN * NN;

    const int prow0 = pbase + w * 16 + gr;
    const int prow1 = prow0 + 8;
    const int ac = quad * 2;

    // ---- A fragments (Hp hi/lo) resident in registers ----
    uint32_t Ahi[8][4], Alo[8][4];
    #pragma unroll
    for (int kc = 0; kc < 8; kc++) {
        Ahi[kc][0] = *(const uint32_t*)&hhB[(size_t)prow0 * DD + kc * 16 + ac];
        Ahi[kc][1] = *(const uint32_t*)&hhB[(size_t)prow1 * DD + kc * 16 + ac];
        Ahi[kc][2] = *(const uint32_t*)&hhB[(size_t)prow0 * DD + kc * 16 + 8 + ac];
        Ahi[kc][3] = *(const uint32_t*)&hhB[(size_t)prow1 * DD + kc * 16 + 8 + ac];
        Alo[kc][0] = *(const uint32_t*)&hlB[(size_t)prow0 * DD + kc * 16 + ac];
        Alo[kc][1] = *(const uint32_t*)&hlB[(size_t)prow1 * DD + kc * 16 + ac];
        Alo[kc][2] = *(const uint32_t*)&hlB[(size_t)prow0 * DD + kc * 16 + 8 + ac];
        Alo[kc][3] = *(const uint32_t*)&hlB[(size_t)prow1 * DD + kc * 16 + 8 + ac];
    }
    const float rp0 = rnB[prow0];
    const float rp1 = rnB[prow1];

    float O[16][4];
    #pragma unroll
    for (int i = 0; i < 16; i++)
        #pragma unroll
        for (int j = 0; j < 4; j++) O[i][j] = 0.0f;

    const uint32_t off1 = (uint32_t)((lane & 7) * (HQS * 2) + (lane >> 3) * 16);
    const uint32_t off2 = (uint32_t)((lane & 15) * (HQS * 2) + (lane >> 4) * 16);

    auto stage = [&](int qb, int buf) {
        const uint32_t dhi = sbase + buf * 2 * TILE_B;
        const uint32_t dlo = dhi + TILE_B;
        #pragma unroll
        for (int i = 0; i < 4; i++) {
            const int idx = i * 256 + t;
            const int r = idx >> 4, c = idx & 15;
            const uint32_t doff = (uint32_t)(r * (HQS * 2) + c * 16);
            CP_ASYNC16(dhi + doff, (const char*)&hhB[(size_t)(qb + r) * DD + c * 8]);
            CP_ASYNC16(dlo + doff, (const char*)&hlB[(size_t)(qb + r) * DD + c * 8]);
        }
        const uint32_t dew = sbase + OFF_EW + buf * STAGE_EW_B;
        #pragma unroll
        for (int i = 0; i < 8; i++) {
            const int idx = i * 256 + t;
            const int r = idx >> 4, c = idx & 15;
            CP_ASYNC16(dew + (uint32_t)(r * (EWS * 4) + c * 16),
                       (const char*)&ewB[(size_t)(pbase + r) * NN + qb + c * 4]);
        }
        if (t < 16)
            CP_ASYNC16(dew + (uint32_t)(EW_B + t * 16), (const char*)&rnB[qb + t * 4]);
    };

    stage(0, 0);
    CP_COMMIT();

    for (int it = 0; it < NN / QT; it++) {
        const int qb = it * QT;
        const int cur = it & 1;
        const uint32_t sHi = sbase + cur * 2 * TILE_B;
        const uint32_t sLo = sHi + TILE_B;
        const float* sewf = (const float*)(smem + OFF_EW + cur * STAGE_EW_B);
        const float* srqf = (const float*)(smem + OFF_EW + cur * STAGE_EW_B + EW_B);

        if (qb + QT < NN) {
            stage(qb + QT, cur ^ 1);   // prefetch into buffer freed last iter
            CP_COMMIT();
            CP_WAIT(1);                // current tile complete; prefetch in flight
        } else {
            CP_WAIT(0);
        }
        __syncthreads();               // buf[cur] (incl. ew/rq) visible to all

        // ---- GEMM1: S = AhiBhi + AloBhi + AhiBlo  (q-column pairs) ----
        float S[8][4];
        #pragma unroll
        for (int i = 0; i < 8; i++)
            #pragma unroll
            for (int j = 0; j < 4; j++) S[i][j] = 0.0f;

        #pragma unroll
        for (int kp = 0; kp < 4; kp++) {
            #pragma unroll
            for (int nc2 = 0; nc2 < 4; nc2++) {
                const int n0 = nc2 * 2, n1 = n0 + 1;
                const uint32_t b0 = (uint32_t)(n0 * 8 * (HQS * 2) + kp * 64) + off1;
                const uint32_t b1 = (uint32_t)(n1 * 8 * (HQS * 2) + kp * 64) + off1;
                uint32_t bh0[4], bh1[4];
                ldsm4(bh0, sHi + b0);
                ldsm4(bh1, sHi + b1);
                mma_bf16(S[n0], Ahi[2 * kp],     bh0 + 0);
                mma_bf16(S[n1], Ahi[2 * kp],     bh1 + 0);
                mma_bf16(S[n0], Ahi[2 * kp + 1], bh0 + 2);
                mma_bf16(S[n1], Ahi[2 * kp + 1], bh1 + 2);
                mma_bf16(S[n0], Alo[2 * kp],     bh0 + 0);
                mma_bf16(S[n1], Alo[2 * kp],     bh1 + 0);
                mma_bf16(S[n0], Alo[2 * kp + 1], bh0 + 2);
                mma_bf16(S[n1], Alo[2 * kp + 1], bh1 + 2);
                uint32_t bl0[4], bl1[4];
                ldsm4(bl0, sLo + b0);
                ldsm4(bl1, sLo + b1);
                mma_bf16(S[n0], Ahi[2 * kp],     bl0 + 0);
                mma_bf16(S[n1], Ahi[2 * kp],     bl1 + 0);
                mma_bf16(S[n0], Ahi[2 * kp + 1], bl0 + 2);
                mma_bf16(S[n1], Ahi[2 * kp + 1], bl1 + 2);
            }
        }

        // ---- mask from smem: S *= rp * rq * ew ----
        const int lr0 = w * 16 + gr;
        #pragma unroll
        for (int nc = 0; nc < 8; nc++) {
            const int col = nc * 8 + ac;
            const float2 e0 = *(const float2*)&sewf[lr0 * EWS + col];
            const float2 e1 = *(const float2*)&sewf[(lr0 + 8) * EWS + col];
            const float2 rq = *(const float2*)&srqf[col];
            S[nc][0] *= rp0 * rq.x * e0.x;
            S[nc][1] *= rp0 * rq.y * e0.y;
            S[nc][2] *= rp1 * rq.x * e1.x;
            S[nc][3] *= rp1 * rq.y * e1.y;
        }

        // ---- split S -> P fragments ----
        uint32_t Phi[4][4], Plo[4][4];
        #pragma unroll
        for (int kc = 0; kc < 4; kc++) {
            split2(S[2 * kc][0],     S[2 * kc][1],     Phi[kc][0], Plo[kc][0]);
            split2(S[2 * kc][2],     S[2 * kc][3],     Phi[kc][1], Plo[kc][1]);
            split2(S[2 * kc + 1][0], S[2 * kc + 1][1], Phi[kc][2], Plo[kc][2]);
            split2(S[2 * kc + 1][2], S[2 * kc + 1][3], Phi[kc][3], Plo[kc][3]);
        }

        // ---- GEMM2: O += PhiBhi + PloBhi + PhiBlo  (4 accumulators round-robin) ----
        #pragma unroll
        for (int kc = 0; kc < 4; kc++) {
            #pragma unroll
            for (int np2 = 0; np2 < 4; np2++) {
                const int np = np2 * 2;
                const uint32_t b0 = (uint32_t)(kc * 16 * (HQS * 2) + np * 32) + off2;
                const uint32_t b1 = b0 + 32;
                uint32_t bh0[4], bh1[4];
                ldsm4t(bh0, sHi + b0);
                ldsm4t(bh1, sHi + b1);
                mma_bf16(O[2 * np],     Phi[kc], bh0 + 0);
                mma_bf16(O[2 * np + 2], Phi[kc], bh1 + 0);
                mma_bf16(O[2 * np + 1], Phi[kc], bh0 + 2);
                mma_bf16(O[2 * np + 3], Phi[kc], bh1 + 2);
                mma_bf16(O[2 * np],     Plo[kc], bh0 + 0);
                mma_bf16(O[2 * np + 2], Plo[kc], bh1 + 0);
                mma_bf16(O[2 * np + 1], Plo[kc], bh0 + 2);
                mma_bf16(O[2 * np + 3], Plo[kc], bh1 + 2);
                uint32_t bl0[4], bl1[4];
                ldsm4t(bl0, sLo + b0);
                ldsm4t(bl1, sLo + b1);
                mma_bf16(O[2 * np],     Phi[kc], bl0 + 0);
                mma_bf16(O[2 * np + 2], Phi[kc], bl1 + 0);
                mma_bf16(O[2 * np + 1], Phi[kc], bl0 + 2);
                mma_bf16(O[2 * np + 3], Phi[kc], bl1 + 2);
            }
        }
        __syncthreads();               // compute done with buf[cur] before restage
    }

    // ---- epilogue ----
    float* outB = out + (size_t)b * NN * DD;
    #pragma unroll
    for (int nc = 0; nc < 16; nc++) {
        float v0 = O[nc][0], v1 = O[nc][1], v2 = O[nc][2], v3 = O[nc][3];
        if (do_relu) {
            v0 = fmaxf(v0, 0.0f); v1 = fmaxf(v1, 0.0f);
            v2 = fmaxf(v2, 0.0f); v3 = fmaxf(v3, 0.0f);
        }
        *(float2*)&outB[(size_t)prow0 * DD + nc * 8 + ac] = make_float2(v0, v1);
        *(float2*)&outB[(size_t)prow1 * DD + nc * 8 + ac] = make_float2(v2, v3);
    }
}

// ---------------------------------------------------------------------------
extern "C" void kernel_launch(void* const* d_in, const int* in_sizes, int n_in,
                              void* d_out, int out_size)
{
    const float* x  = (const float*)d_in[0];
    const float* ew = (const float*)d_in[1];
    const float* W[3]  = {(const float*)d_in[2], (const float*)d_in[4], (const float*)d_in[6]};
    const float* bb[3] = {(const float*)d_in[3], (const float*)d_in[5], (const float*)d_in[7]};
    float* out = (float*)d_out;

    float *buf, *rn;
    __nv_bfloat16 *hhi, *hlo;
    cudaGetSymbolAddress((void**)&buf, g_buf);
    cudaGetSymbolAddress((void**)&rn, g_rn);
    cudaGetSymbolAddress((void**)&hhi, g_hhi);
    cudaGetSymbolAddress((void**)&hlo, g_hlo);

    cudaFuncSetAttribute(linear_norm_kernel,
                         cudaFuncAttributeMaxDynamicSharedMemorySize, SMEM_LIN);
    cudaFuncSetAttribute(fused_mma_kernel,
                         cudaFuncAttributeMaxDynamicSharedMemorySize, SMEM_FUSED);

    const dim3 gl(ROWS_TOT / 64);
    const dim3 gf(NN / 128, NB);

    const float* cur = x;
    for (int l = 0; l < 3; l++) {
        linear_norm_kernel<<<gl, 256, SMEM_LIN>>>(cur, W[l], bb[l], hhi, hlo, rn);
        float* dst = (l == 2) ? out : buf;
        fused_mma_kernel<<<gf, 256, SMEM_FUSED>>>(hhi, hlo, rn, ew, dst, (l < 2) ? 1 : 0);
        cur = buf;
    }
}

// round 9
// speedup vs baseline: 1.0348x; 1.0348x over previous
#include <cuda_runtime.h>
#include <cuda_bf16.h>
#include <cstdint>
#include <math.h>

#define NB 8
#define NN 2048
#define DD 128
#define ROWS_TOT (NB * NN)

__device__ float g_buf[ROWS_TOT * DD];
__device__ __nv_bfloat16 g_hhi[ROWS_TOT * DD];
__device__ __nv_bfloat16 g_hlo[ROWS_TOT * DD];
__device__ float g_rn[ROWS_TOT];

// ---------------------------------------------------------------------------
__device__ __forceinline__ uint32_t smem_u32(const void* p) {
    uint32_t a;
    asm("{ .reg .u64 t; cvta.to.shared.u64 t, %1; cvt.u32.u64 %0, t; }" : "=r"(a) : "l"(p));
    return a;
}
__device__ __forceinline__ void mma_bf16(float* d, const uint32_t* a, const uint32_t* b) {
    asm volatile(
        "mma.sync.aligned.m16n8k16.row.col.f32.bf16.bf16.f32 "
        "{%0,%1,%2,%3}, {%4,%5,%6,%7}, {%8,%9}, {%0,%1,%2,%3};"
        : "+f"(d[0]), "+f"(d[1]), "+f"(d[2]), "+f"(d[3])
        : "r"(a[0]), "r"(a[1]), "r"(a[2]), "r"(a[3]), "r"(b[0]), "r"(b[1]));
}
__device__ __forceinline__ void ldsm4(uint32_t* r, uint32_t addr) {
    asm volatile("ldmatrix.sync.aligned.m8n8.x4.shared.b16 {%0,%1,%2,%3}, [%4];"
                 : "=r"(r[0]), "=r"(r[1]), "=r"(r[2]), "=r"(r[3]) : "r"(addr));
}
__device__ __forceinline__ void ldsm4t(uint32_t* r, uint32_t addr) {
    asm volatile("ldmatrix.sync.aligned.m8n8.x4.trans.shared.b16 {%0,%1,%2,%3}, [%4];"
                 : "=r"(r[0]), "=r"(r[1]), "=r"(r[2]), "=r"(r[3]) : "r"(addr));
}
// fast hi/lo split: one bf16x2 cvt per pair; rounding identical to __float2bfloat16 (rn)
__device__ __forceinline__ void split2f(float v0, float v1, uint32_t& hi, uint32_t& lo) {
    uint32_t h;
    asm("cvt.rn.bf16x2.f32 %0, %1, %2;" : "=r"(h) : "f"(v1), "f"(v0));
    const float f0 = __uint_as_float(h << 16);
    const float f1 = __uint_as_float(h & 0xffff0000u);
    const float r0 = v0 - f0;
    const float r1 = v1 - f1;
    uint32_t l;
    asm("cvt.rn.bf16x2.f32 %0, %1, %2;" : "=r"(l) : "f"(r1), "f"(r0));
    hi = h;
    lo = l;
}
#define CP_ASYNC16(dst, src) \
    asm volatile("cp.async.cg.shared.global [%0], [%1], 16;" :: "r"(dst), "l"(src))
#define CP_COMMIT() asm volatile("cp.async.commit_group;" ::: "memory")
#define CP_WAIT(n)  asm volatile("cp.async.wait_group %0;" :: "n"(n) : "memory")

// ---------------------------------------------------------------------------
// Linear + bias + split + reciprocal norm (unchanged, proven)
// ---------------------------------------------------------------------------
#define SMEM_LIN ((64 * 132 + 128 * 132) * 4)

__global__ __launch_bounds__(256, 2) void linear_norm_kernel(
    const float* __restrict__ in, const float* __restrict__ W, const float* __restrict__ bias,
    __nv_bfloat16* __restrict__ hhi, __nv_bfloat16* __restrict__ hlo, float* __restrict__ rn)
{
    extern __shared__ float sm[];
    float* sx = sm;
    float* sw = sm + 64 * 132;

    const int t = threadIdx.x;
    const int rowbase = blockIdx.x * 64;
    const int f4 = (t & 31) * 4;
    const int r0 = t >> 5;

    #pragma unroll
    for (int r = r0; r < 64; r += 8)
        *(float4*)&sx[r * 132 + f4] = *(const float4*)&in[(size_t)(rowbase + r) * DD + f4];
    #pragma unroll
    for (int r = r0; r < 128; r += 8)
        *(float4*)&sw[r * 132 + f4] = *(const float4*)&W[(size_t)r * DD + f4];
    __syncthreads();

    const int tx = t & 15;
    const int ty = t >> 4;

    float acc[4][8];
    #pragma unroll
    for (int i = 0; i < 4; i++)
        #pragma unroll
        for (int j = 0; j < 8; j++) acc[i][j] = 0.0f;

    #pragma unroll 4
    for (int k = 0; k < DD; k++) {
        float a[4], w[8];
        #pragma unroll
        for (int i = 0; i < 4; i++) a[i] = sx[(ty * 4 + i) * 132 + k];
        #pragma unroll
        for (int j = 0; j < 8; j++) w[j] = sw[k * 132 + tx + 16 * j];
        #pragma unroll
        for (int i = 0; i < 4; i++)
            #pragma unroll
            for (int j = 0; j < 8; j++)
                acc[i][j] = fmaf(a[i], w[j], acc[i][j]);
    }

    float bv[8];
    #pragma unroll
    for (int j = 0; j < 8; j++) bv[j] = bias[tx + 16 * j];

    #pragma unroll
    for (int i = 0; i < 4; i++) {
        float ss = 0.0f;
        #pragma unroll
        for (int j = 0; j < 8; j++) {
            acc[i][j] += bv[j];
            ss = fmaf(acc[i][j], acc[i][j], ss);
        }
        #pragma unroll
        for (int off = 8; off > 0; off >>= 1)
            ss += __shfl_xor_sync(0xffffffffu, ss, off, 16);
        if (tx == 0)
            rn[rowbase + ty * 4 + i] = 1.0f / fmaxf(sqrtf(ss), 1e-12f);
    }

    #pragma unroll
    for (int i = 0; i < 4; i++)
        #pragma unroll
        for (int j = 0; j < 8; j++) {
            const float v = acc[i][j];
            const __nv_bfloat16 h = __float2bfloat16(v);
            const __nv_bfloat16 l = __float2bfloat16(v - __bfloat162float(h));
            const size_t idx = (size_t)(rowbase + ty * 4 + i) * DD + tx + 16 * j;
            hhi[idx] = h;
            hlo[idx] = l;
        }
}

// ---------------------------------------------------------------------------
// Fused flash aggregation. 256 threads = 8 warps, 128 p-rows/CTA, grid 128.
// R5/R8 skeleton; mask+split fused per-chunk into GEMM2 so ptxas can hide
// the ALU/LDS work in HMMA issue gaps.
// ---------------------------------------------------------------------------
#define QT 64
#define HQS 136                         // bf16 elems per smem row (272 B)
#define TILE_B (QT * HQS * 2)           // 17408 B per (hi|lo) Hq tile
#define EWS 72                          // ew smem row stride (floats)
#define EW_B (128 * EWS * 4)
#define RQ_B 256
#define STAGE_EW_B (EW_B + RQ_B)
#define OFF_EW (4 * TILE_B)
#define SMEM_FUSED (OFF_EW + 2 * STAGE_EW_B)

__global__ __launch_bounds__(256, 1) void fused_mma_kernel(
    const __nv_bfloat16* __restrict__ hhi, const __nv_bfloat16* __restrict__ hlo,
    const float* __restrict__ rn, const float* __restrict__ ew,
    float* __restrict__ out, int do_relu)
{
    extern __shared__ char smem[];
    const uint32_t sbase = smem_u32(smem);

    const int t = threadIdx.x;
    const int w = t >> 5;
    const int lane = t & 31;
    const int quad = lane & 3;
    const int gr = lane >> 2;
    const int b = blockIdx.y;
    const int pbase = blockIdx.x * 128;

    const __nv_bfloat16* hhB = hhi + (size_t)b * NN * DD;
    const __nv_bfloat16* hlB = hlo + (size_t)b * NN * DD;
    const float* rnB = rn + (size_t)b * NN;
    const float* ewB = ew + (size_t)b * NN * NN;

    const int prow0 = pbase + w * 16 + gr;
    const int prow1 = prow0 + 8;
    const int ac = quad * 2;

    // ---- A fragments (Hp hi/lo) resident in registers ----
    uint32_t Ahi[8][4], Alo[8][4];
    #pragma unroll
    for (int kc = 0; kc < 8; kc++) {
        Ahi[kc][0] = *(const uint32_t*)&hhB[(size_t)prow0 * DD + kc * 16 + ac];
        Ahi[kc][1] = *(const uint32_t*)&hhB[(size_t)prow1 * DD + kc * 16 + ac];
        Ahi[kc][2] = *(const uint32_t*)&hhB[(size_t)prow0 * DD + kc * 16 + 8 + ac];
        Ahi[kc][3] = *(const uint32_t*)&hhB[(size_t)prow1 * DD + kc * 16 + 8 + ac];
        Alo[kc][0] = *(const uint32_t*)&hlB[(size_t)prow0 * DD + kc * 16 + ac];
        Alo[kc][1] = *(const uint32_t*)&hlB[(size_t)prow1 * DD + kc * 16 + ac];
        Alo[kc][2] = *(const uint32_t*)&hlB[(size_t)prow0 * DD + kc * 16 + 8 + ac];
        Alo[kc][3] = *(const uint32_t*)&hlB[(size_t)prow1 * DD + kc * 16 + 8 + ac];
    }
    const float rp0 = rnB[prow0];
    const float rp1 = rnB[prow1];

    float O[16][4];
    #pragma unroll
    for (int i = 0; i < 16; i++)
        #pragma unroll
        for (int j = 0; j < 4; j++) O[i][j] = 0.0f;

    const uint32_t off1 = (uint32_t)((lane & 7) * (HQS * 2) + (lane >> 3) * 16);
    const uint32_t off2 = (uint32_t)((lane & 15) * (HQS * 2) + (lane >> 4) * 16);

    auto stage = [&](int qb, int buf) {
        const uint32_t dhi = sbase + buf * 2 * TILE_B;
        const uint32_t dlo = dhi + TILE_B;
        #pragma unroll
        for (int i = 0; i < 4; i++) {
            const int idx = i * 256 + t;
            const int r = idx >> 4, c = idx & 15;
            const uint32_t doff = (uint32_t)(r * (HQS * 2) + c * 16);
            CP_ASYNC16(dhi + doff, (const char*)&hhB[(size_t)(qb + r) * DD + c * 8]);
            CP_ASYNC16(dlo + doff, (const char*)&hlB[(size_t)(qb + r) * DD + c * 8]);
        }
        const uint32_t dew = sbase + OFF_EW + buf * STAGE_EW_B;
        #pragma unroll
        for (int i = 0; i < 8; i++) {
            const int idx = i * 256 + t;
            const int r = idx >> 4, c = idx & 15;
            CP_ASYNC16(dew + (uint32_t)(r * (EWS * 4) + c * 16),
                       (const char*)&ewB[(size_t)(pbase + r) * NN + qb + c * 4]);
        }
        if (t < 16)
            CP_ASYNC16(dew + (uint32_t)(EW_B + t * 16), (const char*)&rnB[qb + t * 4]);
    };

    stage(0, 0);
    CP_COMMIT();

    for (int it = 0; it < NN / QT; it++) {
        const int qb = it * QT;
        const int cur = it & 1;
        const uint32_t sHi = sbase + cur * 2 * TILE_B;
        const uint32_t sLo = sHi + TILE_B;
        const float* sewf = (const float*)(smem + OFF_EW + cur * STAGE_EW_B);
        const float* srqf = (const float*)(smem + OFF_EW + cur * STAGE_EW_B + EW_B);

        if (qb + QT < NN) {
            stage(qb + QT, cur ^ 1);   // prefetch into buffer freed last iter
            CP_COMMIT();
            CP_WAIT(1);                // current tile complete; prefetch in flight
        } else {
            CP_WAIT(0);
        }
        __syncthreads();               // buf[cur] (incl. ew/rq) visible to all

        // ---- GEMM1: S = AhiBhi + AloBhi + AhiBlo ----
        float S[8][4];
        #pragma unroll
        for (int i = 0; i < 8; i++)
            #pragma unroll
            for (int j = 0; j < 4; j++) S[i][j] = 0.0f;

        #pragma unroll
        for (int kp = 0; kp < 4; kp++) {
            #pragma unroll
            for (int nc = 0; nc < 8; nc++) {
                const uint32_t base = (uint32_t)(nc * 8 * (HQS * 2) + kp * 64) + off1;
                uint32_t bh[4], bl[4];
                ldsm4(bh, sHi + base);
                mma_bf16(S[nc], Ahi[2 * kp],     bh + 0);
                mma_bf16(S[nc], Ahi[2 * kp + 1], bh + 2);
                mma_bf16(S[nc], Alo[2 * kp],     bh + 0);
                mma_bf16(S[nc], Alo[2 * kp + 1], bh + 2);
                ldsm4(bl, sLo + base);
                mma_bf16(S[nc], Ahi[2 * kp],     bl + 0);
                mma_bf16(S[nc], Ahi[2 * kp + 1], bl + 2);
            }
        }

        // ---- fused mask + split + GEMM2, one k-chunk at a time ----
        const int lr0 = w * 16 + gr;
        #pragma unroll
        for (int kc = 0; kc < 4; kc++) {
            // mask chunk kc (q columns 16kc .. 16kc+15)
            const int n0 = 2 * kc, n1 = n0 + 1;
            uint32_t Phic[4], Ploc[4];
            {
                const int c0 = n0 * 8 + ac;
                const int c1 = n1 * 8 + ac;
                const float2 ea0 = *(const float2*)&sewf[lr0 * EWS + c0];
                const float2 ea1 = *(const float2*)&sewf[(lr0 + 8) * EWS + c0];
                const float2 ra  = *(const float2*)&srqf[c0];
                const float2 eb0 = *(const float2*)&sewf[lr0 * EWS + c1];
                const float2 eb1 = *(const float2*)&sewf[(lr0 + 8) * EWS + c1];
                const float2 rb  = *(const float2*)&srqf[c1];
                const float s00 = S[n0][0] * (rp0 * ra.x * ea0.x);
                const float s01 = S[n0][1] * (rp0 * ra.y * ea0.y);
                const float s02 = S[n0][2] * (rp1 * ra.x * ea1.x);
                const float s03 = S[n0][3] * (rp1 * ra.y * ea1.y);
                const float s10 = S[n1][0] * (rp0 * rb.x * eb0.x);
                const float s11 = S[n1][1] * (rp0 * rb.y * eb0.y);
                const float s12 = S[n1][2] * (rp1 * rb.x * eb1.x);
                const float s13 = S[n1][3] * (rp1 * rb.y * eb1.y);
                split2f(s00, s01, Phic[0], Ploc[0]);
                split2f(s02, s03, Phic[1], Ploc[1]);
                split2f(s10, s11, Phic[2], Ploc[2]);
                split2f(s12, s13, Phic[3], Ploc[3]);
            }
            // GEMM2 chunk kc
            #pragma unroll
            for (int np = 0; np < 8; np++) {
                const uint32_t base = (uint32_t)(kc * 16 * (HQS * 2) + np * 32) + off2;
                uint32_t bh[4], bl[4];
                ldsm4t(bh, sHi + base);
                mma_bf16(O[2 * np],     Phic, bh + 0);
                mma_bf16(O[2 * np + 1], Phic, bh + 2);
                mma_bf16(O[2 * np],     Ploc, bh + 0);
                mma_bf16(O[2 * np + 1], Ploc, bh + 2);
                ldsm4t(bl, sLo + base);
                mma_bf16(O[2 * np],     Phic, bl + 0);
                mma_bf16(O[2 * np + 1], Phic, bl + 2);
            }
        }
        __syncthreads();               // compute done with buf[cur] before restage
    }

    // ---- epilogue ----
    float* outB = out + (size_t)b * NN * DD;
    #pragma unroll
    for (int nc = 0; nc < 16; nc++) {
        float v0 = O[nc][0], v1 = O[nc][1], v2 = O[nc][2], v3 = O[nc][3];
        if (do_relu) {
            v0 = fmaxf(v0, 0.0f); v1 = fmaxf(v1, 0.0f);
            v2 = fmaxf(v2, 0.0f); v3 = fmaxf(v3, 0.0f);
        }
        *(float2*)&outB[(size_t)prow0 * DD + nc * 8 + ac] = make_float2(v0, v1);
        *(float2*)&outB[(size_t)prow1 * DD + nc * 8 + ac] = make_float2(v2, v3);
    }
}

// ---------------------------------------------------------------------------
extern "C" void kernel_launch(void* const* d_in, const int* in_sizes, int n_in,
                              void* d_out, int out_size)
{
    const float* x  = (const float*)d_in[0];
    const float* ew = (const float*)d_in[1];
    const float* W[3]  = {(const float*)d_in[2], (const float*)d_in[4], (const float*)d_in[6]};
    const float* bb[3] = {(const float*)d_in[3], (const float*)d_in[5], (const float*)d_in[7]};
    float* out = (float*)d_out;

    float *buf, *rn;
    __nv_bfloat16 *hhi, *hlo;
    cudaGetSymbolAddress((void**)&buf, g_buf);
    cudaGetSymbolAddress((void**)&rn, g_rn);
    cudaGetSymbolAddress((void**)&hhi, g_hhi);
    cudaGetSymbolAddress((void**)&hlo, g_hlo);

    cudaFuncSetAttribute(linear_norm_kernel,
                         cudaFuncAttributeMaxDynamicSharedMemorySize, SMEM_LIN);
    cudaFuncSetAttribute(fused_mma_kernel,
                         cudaFuncAttributeMaxDynamicSharedMemorySize, SMEM_FUSED);

    const dim3 gl(ROWS_TOT / 64);
    const dim3 gf(NN / 128, NB);

    const float* cur = x;
    for (int l = 0; l < 3; l++) {
        linear_norm_kernel<<<gl, 256, SMEM_LIN>>>(cur, W[l], bb[l], hhi, hlo, rn);
        float* dst = (l == 2) ? out : buf;
        fused_mma_kernel<<<gf, 256, SMEM_FUSED>>>(hhi, hlo, rn, ew, dst, (l < 2) ? 1 : 0);
        cur = buf;
    }
}